// round 17
// baseline (speedup 1.0000x reference)
#include <cuda_runtime.h>
#include <cuda_fp16.h>

#define RES   256
#define FEAT  32
#define NPTS  524288
#define NBA   32
#define NBINS (NBA * NBA * NBA)   // 32768

// Pair-interleaved fp16 planes: cell (y,x) -> 128B block of half2(f(x,c), f(x+1,c))
__device__ __half2  g_pi[3][RES * RES * FEAT];   // 25 MB
__device__ unsigned g_binid[NPTS];
__device__ unsigned g_count[NBINS];              // zero-init; re-zeroed by scan
__device__ unsigned g_offset[NBINS];
__device__ unsigned g_bsum[32];
__device__ float4   g_sdata[NPTS * 2];           // prescaled pixel-space coords/scales

// packed fp32 pair add (sm_103a f32x2 pipe)
__device__ __forceinline__ void addf32x2(float2& a, const float2 b) {
    unsigned long long ua = *reinterpret_cast<const unsigned long long*>(&a);
    unsigned long long ub = *reinterpret_cast<const unsigned long long*>(&b);
    unsigned long long uo;
    asm("add.rn.f32x2 %0, %1, %2;" : "=l"(uo) : "l"(ua), "l"(ub));
    a = *reinterpret_cast<float2*>(&uo);
}

// ---------------- plane interleave: (C,H,W) fp32 -> (H,W,C) half2 x-pairs ----------------
__global__ void interleave_kernel(const float* __restrict__ p0,
                                  const float* __restrict__ p1,
                                  const float* __restrict__ p2) {
    __shared__ float srow[FEAT][RES + 1];
    const float* src = (blockIdx.y == 0) ? p0 : (blockIdx.y == 1 ? p1 : p2);
    __half2* dst = g_pi[blockIdx.y];
    const int y = blockIdx.x;
    const int t = threadIdx.x;

    #pragma unroll
    for (int c = 0; c < FEAT; c++)
        srow[c][t] = src[c * (RES * RES) + y * RES + t];
    __syncthreads();

    #pragma unroll
    for (int i = t; i < RES * FEAT; i += 256) {
        const int x = i >> 5;
        const int c = i & 31;
        const float a = srow[c][x];
        const float b = srow[c][(x + 1 < RES) ? x + 1 : RES - 1];
        dst[(y * RES + x) * FEAT + c] = __floats2half2_rn(a, b);
    }
}

// ---------------- Morton counting sort ----------------
__device__ __forceinline__ unsigned spread3(unsigned v) {
    unsigned r = (v & 1u);
    r |= (v & 2u)  << 2;
    r |= (v & 4u)  << 4;
    r |= (v & 8u)  << 6;
    r |= (v & 16u) << 8;
    return r;
}

__global__ void bin_kernel(const float* __restrict__ pts) {
    int p = blockIdx.x * blockDim.x + threadIdx.x;
    if (p >= NPTS) return;
    const float x = pts[p * 3 + 0];
    const float y = pts[p * 3 + 1];
    const float z = pts[p * 3 + 2];
    const float k = (float)NBA / 2.6f;
    int ix = min(NBA - 1, max(0, (int)((x + 1.3f) * k)));
    int iy = min(NBA - 1, max(0, (int)((y + 1.3f) * k)));
    int iz = min(NBA - 1, max(0, (int)((z + 1.3f) * k)));
    unsigned code = spread3(ix) | (spread3(iy) << 1) | (spread3(iz) << 2);
    g_binid[p] = code;
    atomicAdd(&g_count[code], 1u);
}

// reads g_count, writes local-exclusive scan to g_offset, zeroes g_count
__global__ void scan_block_kernel() {
    __shared__ unsigned sh[1024];
    const int t = threadIdx.x;
    const int i = blockIdx.x * 1024 + t;
    const unsigned v = g_count[i];
    g_count[i] = 0;
    sh[t] = v;
    __syncthreads();
    #pragma unroll
    for (int d = 1; d < 1024; d <<= 1) {
        unsigned add = (t >= d) ? sh[t - d] : 0u;
        __syncthreads();
        sh[t] += add;
        __syncthreads();
    }
    g_offset[i] = sh[t] - v;
    if (t == 1023) g_bsum[blockIdx.x] = sh[t];
}

__global__ void scan_top_kernel() {
    const int t = threadIdx.x;   // 32
    const unsigned v = g_bsum[t];
    unsigned x = v;
    #pragma unroll
    for (int d = 1; d < 32; d <<= 1) {
        unsigned y = __shfl_up_sync(0xffffffffu, x, d);
        if (t >= d) x += y;
    }
    g_bsum[t] = x - v;
}

__global__ void scatter_kernel(const float* __restrict__ pts,
                               const float* __restrict__ scales,
                               const float* __restrict__ aabb) {
    int p = blockIdx.x * blockDim.x + threadIdx.x;
    if (p >= NPTS) return;
    const unsigned bin = g_binid[p];
    const unsigned pos = g_bsum[bin >> 10] + atomicAdd(&g_offset[bin], 1u);

    const float a00 = aabb[0], a01 = aabb[1], a02 = aabb[2];
    const float a10 = aabb[3], a11 = aabb[4], a12 = aabb[5];
    const float n0 = (pts[p * 3 + 0] - a00) * (2.0f / (a10 - a00)) - 1.0f;
    const float n1 = (pts[p * 3 + 1] - a01) * (2.0f / (a11 - a01)) - 1.0f;
    const float n2 = (pts[p * 3 + 2] - a02) * (2.0f / (a12 - a02)) - 1.0f;

    // prescale to pixel space: b = n*127.5 + 127.5, s = scale*127.5
    g_sdata[pos * 2 + 0] = make_float4(fmaf(n0, 127.5f, 127.5f),
                                       fmaf(n1, 127.5f, 127.5f),
                                       fmaf(n2, 127.5f, 127.5f),
                                       scales[p * 3 + 0] * 127.5f);
    g_sdata[pos * 2 + 1] = make_float4(scales[p * 3 + 1] * 127.5f,
                                       scales[p * 3 + 2] * 127.5f,
                                       __int_as_float(p), 0.0f);
}

// ---------------- main sampling kernel ----------------
__host__ __device__ constexpr int SIX(int s) {
    constexpr int t[13] = {2, 0, 1, 3, 4, 2, 2, 2, 2, 3, 3, 1, 1};
    return t[s];
}
__host__ __device__ constexpr int SIY(int s) {
    constexpr int t[13] = {2, 2, 2, 2, 2, 0, 1, 3, 4, 3, 1, 3, 1};
    return t[s];
}

// Block = 32 points. Prep (96 threads: pl=tid>>5, ppt=tid&31) computes per-sample
// records {o0, o1, wp0, wp1} once per point into smem. Main loop per sample:
// 1 broadcast LDS.128 + 2 LDG.128 + HFMA2 chain. Sample-major smem layout ->
// warp reads 4 slots 16B apart (banks 0-15, conflict-free, 8-lane broadcast).
__global__ void __launch_bounds__(256, 3) sample_kernel(float* __restrict__ out)
{
    __shared__ uint4 srec[39][32];   // [pl*13+smp][point] = 19968 B

    const int tid = threadIdx.x;
    const int bp0 = blockIdx.x * 32;

    // ---- prep phase ----
    if (tid < 96) {
        const int pl  = tid >> 5;        // plane 0..2 (one warp each)
        const int ppt = tid & 31;        // local point
        const int gi  = bp0 + ppt;

        const float4 d0 = g_sdata[gi * 2 + 0];
        const float4 d1 = g_sdata[gi * 2 + 1];
        const float nn[3] = { d0.x, d0.y, d0.z };
        const float ss[3] = { d0.w, d1.x, d1.y };

        const int qi = (pl == 2) ? 1 : 0;
        const int ri = (pl == 0) ? 1 : 2;
        const float bx = nn[qi], by = nn[ri];
        const float sx = ss[qi], sy = ss[ri];

        float xw[5], yw[5];
        int   xo[5], yo0[5];
        #pragma unroll
        for (int k = 0; k < 5; k++) {
            const float m = (float)(k - 2) * 0.5f;

            const float cx  = fmaf(sx, m, bx);
            const float x0f = floorf(cx);
            xw[k] = cx - x0f;
            xo[k] = (int)x0f * 8;

            const float cy  = fmaf(sy, m, by);
            const float y0f = floorf(cy);
            yw[k] = cy - y0f;
            yo0[k] = (int)y0f * (RES * 8);
        }

        #pragma unroll
        for (int smp = 0; smp < 13; smp++) {
            const float wx  = xw[SIX(smp)];
            const float wy  = yw[SIY(smp)];
            const float w11 = wx * wy;
            const __half2 wp0 = __floats2half2_rn(1.0f - wx - (wy - w11), wx - w11);
            const __half2 wp1 = __floats2half2_rn(wy - w11, w11);

            uint4 rec;
            rec.x = (unsigned)(yo0[SIY(smp)] + xo[SIX(smp)]);
            rec.y = rec.x + RES * 8;
            rec.z = *reinterpret_cast<const unsigned*>(&wp0);
            rec.w = *reinterpret_cast<const unsigned*>(&wp1);
            srec[pl * 13 + smp][ppt] = rec;
        }
    }
    __syncthreads();

    // ---- main phase ----
    const int lane = tid & 31;
    const int grp  = lane >> 3;
    const int cl   = lane & 7;
    const int lpt  = (tid >> 5) * 4 + grp;
    const int i    = bp0 + lpt;
    const int orig = __float_as_int(g_sdata[i * 2 + 1].z);

    float res[4];
    #pragma unroll
    for (int j = 0; j < 4; j++) res[j] = 1.0f;

    #define H2AT(Q, j)  (*reinterpret_cast<const __half2*>(&(&(Q).x)[j]))
    #define WOF(R, f)   (*reinterpret_cast<const __half2*>(&(R).f))

    #pragma unroll
    for (int pl = 0; pl < 3; pl++) {
        const uint4* __restrict__ base = ((const uint4*)g_pi[pl]) + cl;

        float2 acc[4];
        #pragma unroll
        for (int j = 0; j < 4; j++) { acc[j].x = 0.0f; acc[j].y = 0.0f; }

        // sample 0 alone, flushed
        {
            const uint4 r  = srec[pl * 13 + 0][lpt];
            const uint4 q0 = base[r.x];
            const uint4 q1 = base[r.y];
            #pragma unroll
            for (int j = 0; j < 4; j++) {
                __half2 t = __hmul2(H2AT(q0, j), WOF(r, z));
                t = __hfma2(H2AT(q1, j), WOF(r, w), t);
                addf32x2(acc[j], __half22float2(t));
            }
        }

        // 3 groups of 4 samples: fp16 chain (8 terms), single packed flush
        #pragma unroll
        for (int g = 0; g < 3; g++) {
            const uint4 ra = srec[pl * 13 + 1 + g * 4][lpt];
            const uint4 rb = srec[pl * 13 + 2 + g * 4][lpt];
            const uint4 rc = srec[pl * 13 + 3 + g * 4][lpt];
            const uint4 rd = srec[pl * 13 + 4 + g * 4][lpt];

            const uint4 qa0 = base[ra.x];
            const uint4 qa1 = base[ra.y];
            const uint4 qb0 = base[rb.x];
            const uint4 qb1 = base[rb.y];
            const uint4 qc0 = base[rc.x];
            const uint4 qc1 = base[rc.y];
            const uint4 qd0 = base[rd.x];
            const uint4 qd1 = base[rd.y];

            #pragma unroll
            for (int j = 0; j < 4; j++) {
                __half2 t = __hmul2(H2AT(qa0, j), WOF(ra, z));
                t = __hfma2(H2AT(qa1, j), WOF(ra, w), t);
                t = __hfma2(H2AT(qb0, j), WOF(rb, z), t);
                t = __hfma2(H2AT(qb1, j), WOF(rb, w), t);
                t = __hfma2(H2AT(qc0, j), WOF(rc, z), t);
                t = __hfma2(H2AT(qc1, j), WOF(rc, w), t);
                t = __hfma2(H2AT(qd0, j), WOF(rd, z), t);
                t = __hfma2(H2AT(qd1, j), WOF(rd, w), t);
                addf32x2(acc[j], __half22float2(t));
            }
        }

        #pragma unroll
        for (int j = 0; j < 4; j++)
            res[j] *= (acc[j].x + acc[j].y);
    }
    #undef H2AT
    #undef WOF

    const float inv2197 = 1.0f / 2197.0f;   // (1/13)^3 folded
    float4 o;
    o.x = res[0] * inv2197;
    o.y = res[1] * inv2197;
    o.z = res[2] * inv2197;
    o.w = res[3] * inv2197;
    ((float4*)out)[orig * 8 + cl] = o;
}

extern "C" void kernel_launch(void* const* d_in, const int* in_sizes, int n_in,
                              void* d_out, int out_size) {
    (void)in_sizes; (void)n_in; (void)out_size;
    const float* pts    = (const float*)d_in[0];
    const float* scales = (const float*)d_in[2];
    const float* p0     = (const float*)d_in[3];
    const float* p1     = (const float*)d_in[4];
    const float* p2     = (const float*)d_in[5];
    const float* aabb   = (const float*)d_in[6];
    float* out          = (float*)d_out;

    interleave_kernel<<<dim3(RES, 3), 256>>>(p0, p1, p2);
    bin_kernel<<<NPTS / 256, 256>>>(pts);
    scan_block_kernel<<<NBINS / 1024, 1024>>>();
    scan_top_kernel<<<1, 32>>>();
    scatter_kernel<<<NPTS / 256, 256>>>(pts, scales, aabb);
    sample_kernel<<<NPTS / 32, 256>>>(out);
}